// round 4
// baseline (speedup 1.0000x reference)
#include <cuda_runtime.h>

// Problem constants (fixed by the reference).
#define NN 100000
#define DD 64
#define NE 1600000
#define NROW4 16            // float4s per 64-float row

// Chebyshev coefficients for lambda_max = 2.0 (kept general; constant-fold to
// c1a=-1, c1b=0, c2a=-2, c2b=0).
#define C1A (-2.0f / 2.0f)
#define C1B (2.0f / 2.0f - 1.0f)
#define C2A (-4.0f / 2.0f)
#define C2B (4.0f / 2.0f - 2.0f)

// Scratch (device globals: no allocation allowed in kernel_launch).
__device__ float  g_deg [NN];
__device__ float  g_norm[NN];
__device__ float4 g_xs  [NN * NROW4];   // scaled features (reused between passes)
__device__ float4 g_h0  [NN * NROW4];   // scatter result pass 1
__device__ float4 g_h1  [NN * NROW4];   // scatter result pass 2

typedef unsigned long long ull;

// ---------------------------------------------------------------------------
// f32x2 packed-FMA helpers (Blackwell)
// ---------------------------------------------------------------------------
__device__ __forceinline__ ull pack2(float v) {
    ull r;
    asm("mov.b64 %0, {%1, %1};" : "=l"(r) : "f"(v));
    return r;
}
__device__ __forceinline__ void fma2(ull& d, ull a, ull b) {
    asm("fma.rn.f32x2 %0, %1, %2, %0;" : "+l"(d) : "l"(a), "l"(b));
}
__device__ __forceinline__ float2 unpack2(ull v) {
    float2 r;
    asm("mov.b64 {%0, %1}, %2;" : "=f"(r.x), "=f"(r.y) : "l"(v));
    return r;
}

// ---------------------------------------------------------------------------
// 1) degree histogram: deg[dst] += 1
// ---------------------------------------------------------------------------
__global__ void deg_kernel(const int4* __restrict__ dst4) {
    int t = blockIdx.x * blockDim.x + threadIdx.x;
    if (t < NE / 4) {
        int4 d = __ldg(dst4 + t);
        atomicAdd(&g_deg[d.x], 1.0f);
        atomicAdd(&g_deg[d.y], 1.0f);
        atomicAdd(&g_deg[d.z], 1.0f);
        atomicAdd(&g_deg[d.w], 1.0f);
    }
}

// ---------------------------------------------------------------------------
// 2) norm = rsqrt(max(deg,1));  xs = feat * norm   (row-scaled features)
// ---------------------------------------------------------------------------
__global__ void scale_kernel(const float4* __restrict__ feat4) {
    int t = blockIdx.x * blockDim.x + threadIdx.x;
    if (t < NN * NROW4) {
        int i = t >> 4;
        float nv = rsqrtf(fmaxf(g_deg[i], 1.0f));
        float4 f = __ldg(feat4 + t);
        f.x *= nv; f.y *= nv; f.z *= nv; f.w *= nv;
        g_xs[t] = f;
        if ((t & 15) == 0) g_norm[i] = nv;
    }
}

// ---------------------------------------------------------------------------
// 3) scatter: h[dst] += g_xs[src]  (16B vector reductions; one thread per
//    (edge, float4-chunk); 16 consecutive threads share one edge).
//    PASS selects destination buffer so no scratch pointers cross the ABI.
// ---------------------------------------------------------------------------
template <int PASS>
__global__ void scatter_kernel(const int* __restrict__ src,
                               const int* __restrict__ dst) {
    int t = blockIdx.x * blockDim.x + threadIdx.x;
    if (t < NE * NROW4) {
        int e = t >> 4;
        int c = t & 15;
        int s = __ldg(src + e);
        int d = __ldg(dst + e);
        float4 v = g_xs[(s << 4) + c];
        float4* hp = (PASS == 0 ? g_h0 : g_h1) + (d << 4) + c;
        float* p = reinterpret_cast<float*>(hp);
        asm volatile("red.global.add.v4.f32 [%0], {%1, %2, %3, %4};"
                     :: "l"(p), "f"(v.x), "f"(v.y), "f"(v.z), "f"(v.w)
                     : "memory");
    }
}

// ---------------------------------------------------------------------------
// 4) xs <- Tx1 * norm, where Tx1 = c1a*norm*h0 + c1b*feat
// ---------------------------------------------------------------------------
__global__ void rescale_kernel(const float4* __restrict__ feat4) {
    int t = blockIdx.x * blockDim.x + threadIdx.x;
    if (t < NN * NROW4) {
        int i = t >> 4;
        float nv = g_norm[i];
        float a = C1A * nv;
        float4 h = g_h0[t];
        float4 f = __ldg(feat4 + t);
        float4 r;
        r.x = (a * h.x + C1B * f.x) * nv;
        r.y = (a * h.y + C1B * f.y) * nv;
        r.z = (a * h.z + C1B * f.z) * nv;
        r.w = (a * h.w + C1B * f.w) * nv;
        g_xs[t] = r;
    }
}

// ---------------------------------------------------------------------------
// 5) fused epilogue GEMM:
//    t0 = feat;  t1 = c1a*n*h0 + c1b*t0;  t2 = c2a*n*h1 + c2b*t1 - t0
//    out = t0@W0 + t1@W1 + t2@W2 + bias
//    Block: 256 threads = 4 col-groups (16 cols, warp-uniform) x 64 row-groups
//    (4 rows each). W (48KB) in shared; packed f32x2 accumulators.
// ---------------------------------------------------------------------------
__global__ __launch_bounds__(256) void final_kernel(
    const float4* __restrict__ feat4,
    const float4* __restrict__ W4,
    const float4* __restrict__ bias4,
    float4* __restrict__ out4) {
    __shared__ __align__(16) float Ws[3 * 64 * 64];   // 49152 B
    {
        float4* Ws4 = reinterpret_cast<float4*>(Ws);
        for (int i = threadIdx.x; i < 3 * 64 * 16; i += 256)
            Ws4[i] = __ldg(W4 + i);
    }
    __syncthreads();

    const int cg   = threadIdx.x >> 6;   // col group: cols [16*cg, 16*cg+16)
    const int rg   = threadIdx.x & 63;
    const int base = blockIdx.x * 256;

    int   rows[4];
    bool  valid[4];
    float n[4];
#pragma unroll
    for (int r = 0; r < 4; r++) {
        int row  = base + rg + 64 * r;
        valid[r] = row < NN;
        rows[r]  = valid[r] ? row : 0;
        n[r]     = g_norm[rows[r]];
    }

    ull acc[4][8];
#pragma unroll
    for (int r = 0; r < 4; r++)
#pragma unroll
        for (int cp = 0; cp < 8; cp++) acc[r][cp] = 0ULL;

    const ulonglong2* Wp = reinterpret_cast<const ulonglong2*>(Ws);
    // ulonglong2 index: float index / 4 = k*1024 + d*16 + cg*4 + j

    for (int dc = 0; dc < 16; dc++) {          // d in chunks of 4
        float4 a0[4], a1[4], a2[4];
#pragma unroll
        for (int r = 0; r < 4; r++) {
            int b = (rows[r] << 4) + dc;
            a0[r] = __ldg(feat4 + b);
            a1[r] = g_h0[b];
            a2[r] = g_h1[b];
        }
#pragma unroll
        for (int s = 0; s < 4; s++) {
            const int d = dc * 4 + s;
            ull tt[3][4];
#pragma unroll
            for (int r = 0; r < 4; r++) {
                float t0  = reinterpret_cast<const float*>(&a0[r])[s];
                float h0v = reinterpret_cast<const float*>(&a1[r])[s];
                float h1v = reinterpret_cast<const float*>(&a2[r])[s];
                float t1 = fmaf(C1A * n[r], h0v, C1B * t0);
                float t2 = fmaf(C2A * n[r], h1v, fmaf(C2B, t1, -t0));
                tt[0][r] = pack2(t0);
                tt[1][r] = pack2(t1);
                tt[2][r] = pack2(t2);
            }
#pragma unroll
            for (int k = 0; k < 3; k++) {
                const ulonglong2* p = Wp + (k * 1024 + d * 16 + cg * 4);
                ull w[8];
#pragma unroll
                for (int j = 0; j < 4; j++) {
                    ulonglong2 v = p[j];       // LDS.128, warp-uniform broadcast
                    w[2 * j]     = v.x;
                    w[2 * j + 1] = v.y;
                }
#pragma unroll
                for (int r = 0; r < 4; r++)
#pragma unroll
                    for (int cp = 0; cp < 8; cp++)
                        fma2(acc[r][cp], tt[k][r], w[cp]);
            }
        }
    }

    float4 b4[4];
#pragma unroll
    for (int j = 0; j < 4; j++) b4[j] = __ldg(bias4 + cg * 4 + j);
#pragma unroll
    for (int r = 0; r < 4; r++) {
        if (!valid[r]) continue;
#pragma unroll
        for (int j = 0; j < 4; j++) {
            float2 lo = unpack2(acc[r][2 * j]);
            float2 hi = unpack2(acc[r][2 * j + 1]);
            float4 o;
            o.x = lo.x + b4[j].x;
            o.y = lo.y + b4[j].y;
            o.z = hi.x + b4[j].z;
            o.w = hi.y + b4[j].w;
            out4[(rows[r] << 4) + cg * 4 + j] = o;
        }
    }
}

// ---------------------------------------------------------------------------
// launch (graph-capturable: only async memsets + kernel launches)
// ---------------------------------------------------------------------------
extern "C" void kernel_launch(void* const* d_in, const int* in_sizes, int n_in,
                              void* d_out, int out_size) {
    const float* feat = (const float*)d_in[0];
    const float* W    = (const float*)d_in[1];
    const float* bias = (const float*)d_in[2];
    const int*   esrc = (const int*)d_in[3];
    const int*   edst = (const int*)d_in[4];
    float*       out  = (float*)d_out;

    void *p_deg = nullptr, *p_h0 = nullptr, *p_h1 = nullptr;
    cudaGetSymbolAddress(&p_deg, g_deg);
    cudaGetSymbolAddress(&p_h0,  g_h0);
    cudaGetSymbolAddress(&p_h1,  g_h1);
    cudaMemsetAsync(p_deg, 0, NN * sizeof(float));
    cudaMemsetAsync(p_h0,  0, NN * DD * sizeof(float));
    cudaMemsetAsync(p_h1,  0, NN * DD * sizeof(float));

    const int T = 256;

    deg_kernel<<<(NE / 4 + T - 1) / T, T>>>((const int4*)edst);
    scale_kernel<<<(NN * NROW4 + T - 1) / T, T>>>((const float4*)feat);
    scatter_kernel<0><<<(NE * NROW4 + T - 1) / T, T>>>(esrc, edst);
    rescale_kernel<<<(NN * NROW4 + T - 1) / T, T>>>((const float4*)feat);
    scatter_kernel<1><<<(NE * NROW4 + T - 1) / T, T>>>(esrc, edst);
    final_kernel<<<(NN + 255) / 256, 256>>>((const float4*)feat,
                                            (const float4*)W,
                                            (const float4*)bias,
                                            (float4*)out);
}

// round 5
// speedup vs baseline: 1.4772x; 1.4772x over previous
#include <cuda_runtime.h>

// Problem constants (fixed by the reference).
#define NN 100000
#define DD 64
#define NE 1600000
#define NROW4 16            // float4s per 64-float row
#define NB 98               // ceil(NN / 1024) scan blocks

// Chebyshev coefficients for lambda_max = 2.0 (constant-fold: C1A=-1, C1B=0,
// C2A=-2, C2B=0).
#define C1A (-2.0f / 2.0f)
#define C1B (2.0f / 2.0f - 1.0f)
#define C2A (-4.0f / 2.0f)
#define C2B (4.0f / 2.0f - 2.0f)

// Scratch (device globals: no allocation allowed in kernel_launch).
__device__ int    g_degi  [NN];
__device__ int    g_bsum  [128];        // per-scan-block sums (NB used)
__device__ int    g_boff  [128];        // exclusive scan of g_bsum
__device__ int    g_rowptr[NN + 1];
__device__ int    g_cursor[NN];
__device__ int    g_adj   [NE];
__device__ float  g_norm  [NN];
__device__ float4 g_xsA   [NN * NROW4]; // feat * norm
__device__ float4 g_xsB   [NN * NROW4]; // Tx1 * norm
__device__ float4 g_h0    [NN * NROW4]; // raw aggregation sums, pass 1
__device__ float4 g_h1    [NN * NROW4]; // raw aggregation sums, pass 2

typedef unsigned long long ull;

// ---------------------------------------------------------------------------
// f32x2 packed-FMA helpers (Blackwell)
// ---------------------------------------------------------------------------
__device__ __forceinline__ ull pack2(float v) {
    ull r;
    asm("mov.b64 %0, {%1, %1};" : "=l"(r) : "f"(v));
    return r;
}
__device__ __forceinline__ void fma2(ull& d, ull a, ull b) {
    asm("fma.rn.f32x2 %0, %1, %2, %0;" : "+l"(d) : "l"(a), "l"(b));
}
__device__ __forceinline__ float2 unpack2(ull v) {
    float2 r;
    asm("mov.b64 {%0, %1}, %2;" : "=f"(r.x), "=f"(r.y) : "l"(v));
    return r;
}

// ---------------------------------------------------------------------------
// 1) degree histogram (int): deg[dst] += 1
// ---------------------------------------------------------------------------
__global__ void deg_kernel(const int4* __restrict__ dst4) {
    int t = blockIdx.x * blockDim.x + threadIdx.x;
    if (t < NE / 4) {
        int4 d = __ldg(dst4 + t);
        atomicAdd(&g_degi[d.x], 1);
        atomicAdd(&g_degi[d.y], 1);
        atomicAdd(&g_degi[d.z], 1);
        atomicAdd(&g_degi[d.w], 1);
    }
}

// ---------------------------------------------------------------------------
// 2a) per-block degree sums (1024 elements per block)
// ---------------------------------------------------------------------------
__global__ __launch_bounds__(1024) void blocksum_kernel() {
    __shared__ int sh[1024];
    int tid = threadIdx.x;
    int i = blockIdx.x * 1024 + tid;
    sh[tid] = (i < NN) ? g_degi[i] : 0;
    __syncthreads();
    for (int off = 512; off > 0; off >>= 1) {
        if (tid < off) sh[tid] += sh[tid + off];
        __syncthreads();
    }
    if (tid == 0) g_bsum[blockIdx.x] = sh[0];
}

// ---------------------------------------------------------------------------
// 2b) exclusive scan of the NB block sums (one block)
// ---------------------------------------------------------------------------
__global__ __launch_bounds__(128) void scanbsum_kernel() {
    __shared__ int sh[128];
    int tid = threadIdx.x;
    int v = (tid < NB) ? g_bsum[tid] : 0;
    sh[tid] = v;
    __syncthreads();
    for (int off = 1; off < 128; off <<= 1) {
        int x = (tid >= off) ? sh[tid - off] : 0;
        __syncthreads();
        sh[tid] += x;
        __syncthreads();
    }
    g_boff[tid] = sh[tid] - v;   // exclusive
}

// ---------------------------------------------------------------------------
// 2c) per-block exclusive scan -> row_ptr, cursor
// ---------------------------------------------------------------------------
__global__ __launch_bounds__(1024) void scanblock_kernel() {
    __shared__ int sh[1024];
    int tid = threadIdx.x;
    int i = blockIdx.x * 1024 + tid;
    int v = (i < NN) ? g_degi[i] : 0;
    sh[tid] = v;
    __syncthreads();
    for (int off = 1; off < 1024; off <<= 1) {
        int x = (tid >= off) ? sh[tid - off] : 0;
        __syncthreads();
        sh[tid] += x;
        __syncthreads();
    }
    if (i < NN) {
        int ex = g_boff[blockIdx.x] + sh[tid] - v;
        g_rowptr[i] = ex;
        g_cursor[i] = ex;
    }
    if (i == 0) g_rowptr[NN] = NE;
}

// ---------------------------------------------------------------------------
// 3) CSR fill: adj[cursor[dst]++] = src
// ---------------------------------------------------------------------------
__global__ void fill_kernel(const int4* __restrict__ src4,
                            const int4* __restrict__ dst4) {
    int t = blockIdx.x * blockDim.x + threadIdx.x;
    if (t < NE / 4) {
        int4 s = __ldg(src4 + t);
        int4 d = __ldg(dst4 + t);
        g_adj[atomicAdd(&g_cursor[d.x], 1)] = s.x;
        g_adj[atomicAdd(&g_cursor[d.y], 1)] = s.y;
        g_adj[atomicAdd(&g_cursor[d.z], 1)] = s.z;
        g_adj[atomicAdd(&g_cursor[d.w], 1)] = s.w;
    }
}

// ---------------------------------------------------------------------------
// 4) norm = rsqrt(max(deg,1));  xsA = feat * norm
// ---------------------------------------------------------------------------
__global__ void scale_kernel(const float4* __restrict__ feat4) {
    int t = blockIdx.x * blockDim.x + threadIdx.x;
    if (t < NN * NROW4) {
        int i = t >> 4;
        float nv = rsqrtf(fmaxf((float)g_degi[i], 1.0f));
        float4 f = __ldg(feat4 + t);
        f.x *= nv; f.y *= nv; f.z *= nv; f.w *= nv;
        g_xsA[t] = f;
        if ((t & 15) == 0) g_norm[i] = nv;
    }
}

// ---------------------------------------------------------------------------
// 5) gather: 16 threads per node walk the neighbor list, accumulating xs rows
//    in registers. PASS 0: write h0 (raw sum) and the next-level scaled
//    features xsB = (C1A*n*h0 + C1B*feat)*n.  PASS 1: write h1 only.
// ---------------------------------------------------------------------------
template <int PASS>
__global__ __launch_bounds__(256) void gather_kernel(const float4* __restrict__ feat4) {
    int t = blockIdx.x * blockDim.x + threadIdx.x;
    if (t >= NN * NROW4) return;
    int i = t >> 4;
    int c = t & 15;

    int j   = g_rowptr[i];
    int end = g_rowptr[i + 1];
    const float4* __restrict__ xs = (PASS == 0) ? g_xsA : g_xsB;

    float4 acc = make_float4(0.f, 0.f, 0.f, 0.f);
    // Unroll x4: 4 independent 16B loads in flight against ~234-cyc L2 latency.
    for (; j + 4 <= end; j += 4) {
        int s0 = g_adj[j], s1 = g_adj[j + 1], s2 = g_adj[j + 2], s3 = g_adj[j + 3];
        float4 v0 = xs[(s0 << 4) + c];
        float4 v1 = xs[(s1 << 4) + c];
        float4 v2 = xs[(s2 << 4) + c];
        float4 v3 = xs[(s3 << 4) + c];
        acc.x += (v0.x + v1.x) + (v2.x + v3.x);
        acc.y += (v0.y + v1.y) + (v2.y + v3.y);
        acc.z += (v0.z + v1.z) + (v2.z + v3.z);
        acc.w += (v0.w + v1.w) + (v2.w + v3.w);
    }
    for (; j < end; j++) {
        int s = g_adj[j];
        float4 v = xs[(s << 4) + c];
        acc.x += v.x; acc.y += v.y; acc.z += v.z; acc.w += v.w;
    }

    if (PASS == 0) {
        g_h0[t] = acc;
        float nv = g_norm[i];
        float a  = C1A * nv;
        float4 f = __ldg(feat4 + t);   // dead when C1B==0; compiler folds
        float4 r;
        r.x = (a * acc.x + C1B * f.x) * nv;
        r.y = (a * acc.y + C1B * f.y) * nv;
        r.z = (a * acc.z + C1B * f.z) * nv;
        r.w = (a * acc.w + C1B * f.w) * nv;
        g_xsB[t] = r;
    } else {
        g_h1[t] = acc;
    }
}

// ---------------------------------------------------------------------------
// 6) fused epilogue GEMM:
//    t0 = feat;  t1 = c1a*n*h0 + c1b*t0;  t2 = c2a*n*h1 + c2b*t1 - t0
//    out = t0@W0 + t1@W1 + t2@W2 + bias
//    256 threads = 4 col-groups (16 cols, warp-uniform) x 64 row-groups
//    (4 rows each). W (48KB) in shared; packed f32x2 accumulators.
// ---------------------------------------------------------------------------
__global__ __launch_bounds__(256) void final_kernel(
    const float4* __restrict__ feat4,
    const float4* __restrict__ W4,
    const float4* __restrict__ bias4,
    float4* __restrict__ out4) {
    __shared__ __align__(16) float Ws[3 * 64 * 64];   // 49152 B
    {
        float4* Ws4 = reinterpret_cast<float4*>(Ws);
        for (int i = threadIdx.x; i < 3 * 64 * 16; i += 256)
            Ws4[i] = __ldg(W4 + i);
    }
    __syncthreads();

    const int cg   = threadIdx.x >> 6;
    const int rg   = threadIdx.x & 63;
    const int base = blockIdx.x * 256;

    int   rows[4];
    bool  valid[4];
    float n[4];
#pragma unroll
    for (int r = 0; r < 4; r++) {
        int row  = base + rg + 64 * r;
        valid[r] = row < NN;
        rows[r]  = valid[r] ? row : 0;
        n[r]     = g_norm[rows[r]];
    }

    ull acc[4][8];
#pragma unroll
    for (int r = 0; r < 4; r++)
#pragma unroll
        for (int cp = 0; cp < 8; cp++) acc[r][cp] = 0ULL;

    const ulonglong2* Wp = reinterpret_cast<const ulonglong2*>(Ws);

    for (int dc = 0; dc < 16; dc++) {
        float4 a0[4], a1[4], a2[4];
#pragma unroll
        for (int r = 0; r < 4; r++) {
            int b = (rows[r] << 4) + dc;
            a0[r] = __ldg(feat4 + b);
            a1[r] = g_h0[b];
            a2[r] = g_h1[b];
        }
#pragma unroll
        for (int s = 0; s < 4; s++) {
            const int d = dc * 4 + s;
            ull tt[3][4];
#pragma unroll
            for (int r = 0; r < 4; r++) {
                float t0  = reinterpret_cast<const float*>(&a0[r])[s];
                float h0v = reinterpret_cast<const float*>(&a1[r])[s];
                float h1v = reinterpret_cast<const float*>(&a2[r])[s];
                float t1 = fmaf(C1A * n[r], h0v, C1B * t0);
                float t2 = fmaf(C2A * n[r], h1v, fmaf(C2B, t1, -t0));
                tt[0][r] = pack2(t0);
                tt[1][r] = pack2(t1);
                tt[2][r] = pack2(t2);
            }
#pragma unroll
            for (int k = 0; k < 3; k++) {
                const ulonglong2* p = Wp + (k * 1024 + d * 16 + cg * 4);
                ull w[8];
#pragma unroll
                for (int j = 0; j < 4; j++) {
                    ulonglong2 v = p[j];       // LDS.128, warp-uniform broadcast
                    w[2 * j]     = v.x;
                    w[2 * j + 1] = v.y;
                }
#pragma unroll
                for (int r = 0; r < 4; r++)
#pragma unroll
                    for (int cp = 0; cp < 8; cp++)
                        fma2(acc[r][cp], tt[k][r], w[cp]);
            }
        }
    }

    float4 b4[4];
#pragma unroll
    for (int j = 0; j < 4; j++) b4[j] = __ldg(bias4 + cg * 4 + j);
#pragma unroll
    for (int r = 0; r < 4; r++) {
        if (!valid[r]) continue;
#pragma unroll
        for (int j = 0; j < 4; j++) {
            float2 lo = unpack2(acc[r][2 * j]);
            float2 hi = unpack2(acc[r][2 * j + 1]);
            float4 o;
            o.x = lo.x + b4[j].x;
            o.y = lo.y + b4[j].y;
            o.z = hi.x + b4[j].z;
            o.w = hi.y + b4[j].w;
            out4[(rows[r] << 4) + cg * 4 + j] = o;
        }
    }
}

// ---------------------------------------------------------------------------
// launch (graph-capturable: only async memset + kernel launches)
// ---------------------------------------------------------------------------
extern "C" void kernel_launch(void* const* d_in, const int* in_sizes, int n_in,
                              void* d_out, int out_size) {
    const float* feat = (const float*)d_in[0];
    const float* W    = (const float*)d_in[1];
    const float* bias = (const float*)d_in[2];
    const int*   esrc = (const int*)d_in[3];
    const int*   edst = (const int*)d_in[4];
    float*       out  = (float*)d_out;

    void* p_degi = nullptr;
    cudaGetSymbolAddress(&p_degi, g_degi);
    cudaMemsetAsync(p_degi, 0, NN * sizeof(int));

    const int T = 256;

    deg_kernel<<<(NE / 4 + T - 1) / T, T>>>((const int4*)edst);
    blocksum_kernel<<<NB, 1024>>>();
    scanbsum_kernel<<<1, 128>>>();
    scanblock_kernel<<<NB, 1024>>>();
    fill_kernel<<<(NE / 4 + T - 1) / T, T>>>((const int4*)esrc, (const int4*)edst);

    scale_kernel<<<(NN * NROW4 + T - 1) / T, T>>>((const float4*)feat);
    gather_kernel<0><<<(NN * NROW4 + T - 1) / T, T>>>((const float4*)feat);
    gather_kernel<1><<<(NN * NROW4 + T - 1) / T, T>>>((const float4*)feat);

    final_kernel<<<(NN + 255) / 256, 256>>>((const float4*)feat,
                                            (const float4*)W,
                                            (const float4*)bias,
                                            (float4*)out);
}

// round 6
// speedup vs baseline: 1.5042x; 1.0183x over previous
#include <cuda_runtime.h>

// Problem constants (fixed by the reference).
#define NN 100000
#define DD 64
#define NROW4 16            // float4s per 64-float row
#define NE 1600000
#define NB 98               // ceil(NN / 1024) scan blocks

// Chebyshev coefficients for lambda_max = 2.0 (constant-fold: C1A=-1, C1B=0,
// C2A=-2, C2B=0).
#define C1A (-2.0f / 2.0f)
#define C1B (2.0f / 2.0f - 1.0f)
#define C2A (-4.0f / 2.0f)
#define C2B (4.0f / 2.0f - 2.0f)

// Scratch (device globals: no allocation allowed in kernel_launch).
__device__ int    g_degi  [NN];
__device__ int    g_bsum  [128];        // per-scan-block sums (NB used)
__device__ int    g_boff  [128];        // exclusive scan of g_bsum
__device__ int    g_rowptr[NN + 1];
__device__ int    g_cursor[NN];
__device__ int    g_adj   [NE];
__device__ float  g_norm  [NN];
__device__ float  g_norm2 [NN];
__device__ float4 g_h0    [NN * NROW4]; // raw aggregation sums, pass 1
__device__ float4 g_h1    [NN * NROW4]; // aggregation sums, pass 2

typedef unsigned long long ull;

// ---------------------------------------------------------------------------
// f32x2 packed-FMA helpers (Blackwell)
// ---------------------------------------------------------------------------
__device__ __forceinline__ ull pack2(float v) {
    ull r;
    asm("mov.b64 %0, {%1, %1};" : "=l"(r) : "f"(v));
    return r;
}
__device__ __forceinline__ void fma2(ull& d, ull a, ull b) {
    asm("fma.rn.f32x2 %0, %1, %2, %0;" : "+l"(d) : "l"(a), "l"(b));
}
__device__ __forceinline__ float2 unpack2(ull v) {
    float2 r;
    asm("mov.b64 {%0, %1}, %2;" : "=f"(r.x), "=f"(r.y) : "l"(v));
    return r;
}

// ---------------------------------------------------------------------------
// 1) degree histogram (int): deg[dst] += 1
// ---------------------------------------------------------------------------
__global__ void deg_kernel(const int4* __restrict__ dst4) {
    int t = blockIdx.x * blockDim.x + threadIdx.x;
    if (t < NE / 4) {
        int4 d = __ldg(dst4 + t);
        atomicAdd(&g_degi[d.x], 1);
        atomicAdd(&g_degi[d.y], 1);
        atomicAdd(&g_degi[d.z], 1);
        atomicAdd(&g_degi[d.w], 1);
    }
}

// ---------------------------------------------------------------------------
// 1b) norm = rsqrt(max(deg,1)); norm2 = norm*norm
// ---------------------------------------------------------------------------
__global__ void norm_kernel() {
    int i = blockIdx.x * blockDim.x + threadIdx.x;
    if (i < NN) {
        float nv = rsqrtf(fmaxf((float)g_degi[i], 1.0f));
        g_norm[i]  = nv;
        g_norm2[i] = nv * nv;
    }
}

// ---------------------------------------------------------------------------
// 2a) per-block degree sums (1024 elements per block, shuffle reduction)
// ---------------------------------------------------------------------------
__global__ __launch_bounds__(1024) void blocksum_kernel() {
    __shared__ int wsum[32];
    int tid = threadIdx.x, lane = tid & 31, wid = tid >> 5;
    int i = blockIdx.x * 1024 + tid;
    int v = (i < NN) ? g_degi[i] : 0;
#pragma unroll
    for (int off = 16; off > 0; off >>= 1)
        v += __shfl_down_sync(~0u, v, off);
    if (lane == 0) wsum[wid] = v;
    __syncthreads();
    if (wid == 0) {
        int w = wsum[lane];
#pragma unroll
        for (int off = 16; off > 0; off >>= 1)
            w += __shfl_down_sync(~0u, w, off);
        if (lane == 0) g_bsum[blockIdx.x] = w;
    }
}

// ---------------------------------------------------------------------------
// 2b) exclusive scan of the NB block sums (one block, shuffle scan)
// ---------------------------------------------------------------------------
__global__ __launch_bounds__(128) void scanbsum_kernel() {
    __shared__ int wtot[4];
    int tid = threadIdx.x, lane = tid & 31, wid = tid >> 5;
    int v = (tid < NB) ? g_bsum[tid] : 0;
    int x = v;
#pragma unroll
    for (int off = 1; off < 32; off <<= 1) {
        int y = __shfl_up_sync(~0u, x, off);
        if (lane >= off) x += y;
    }
    if (lane == 31) wtot[wid] = x;
    __syncthreads();
    int add = 0;
    for (int w = 0; w < wid; w++) add += wtot[w];
    g_boff[tid] = add + x - v;   // exclusive
}

// ---------------------------------------------------------------------------
// 2c) per-block exclusive scan -> row_ptr, cursor (shuffle scan)
// ---------------------------------------------------------------------------
__global__ __launch_bounds__(1024) void scanblock_kernel() {
    __shared__ int wsum[32];
    int tid = threadIdx.x, lane = tid & 31, wid = tid >> 5;
    int i = blockIdx.x * 1024 + tid;
    int v = (i < NN) ? g_degi[i] : 0;
    int x = v;
#pragma unroll
    for (int off = 1; off < 32; off <<= 1) {
        int y = __shfl_up_sync(~0u, x, off);
        if (lane >= off) x += y;
    }
    if (lane == 31) wsum[wid] = x;
    __syncthreads();
    if (wid == 0) {
        int w = wsum[lane];
#pragma unroll
        for (int off = 1; off < 32; off <<= 1) {
            int y = __shfl_up_sync(~0u, w, off);
            if (lane >= off) w += y;
        }
        wsum[lane] = w;
    }
    __syncthreads();
    int warpoff = (wid > 0) ? wsum[wid - 1] : 0;
    if (i < NN) {
        int ex = g_boff[blockIdx.x] + warpoff + x - v;
        g_rowptr[i] = ex;
        g_cursor[i] = ex;
    }
    if (i == 0 && blockIdx.x == 0) g_rowptr[NN] = NE;
}

// ---------------------------------------------------------------------------
// 3) CSR fill: adj[cursor[dst]++] = src
// ---------------------------------------------------------------------------
__global__ void fill_kernel(const int4* __restrict__ src4,
                            const int4* __restrict__ dst4) {
    int t = blockIdx.x * blockDim.x + threadIdx.x;
    if (t < NE / 4) {
        int4 s = __ldg(src4 + t);
        int4 d = __ldg(dst4 + t);
        g_adj[atomicAdd(&g_cursor[d.x], 1)] = s.x;
        g_adj[atomicAdd(&g_cursor[d.y], 1)] = s.y;
        g_adj[atomicAdd(&g_cursor[d.z], 1)] = s.z;
        g_adj[atomicAdd(&g_cursor[d.w], 1)] = s.w;
    }
}

// ---------------------------------------------------------------------------
// 4) gather pass 0: h0[i] = sum_{s in N(i)} norm[s] * feat[s]
//    16 threads per node; each thread owns one float4 chunk; per-edge norm is
//    a warp-broadcast 4B load. 4 edges in flight, independent accumulators.
// ---------------------------------------------------------------------------
__global__ __launch_bounds__(256) void gather0_kernel(const float4* __restrict__ feat4) {
    int t = blockIdx.x * blockDim.x + threadIdx.x;
    if (t >= NN * NROW4) return;
    int i = t >> 4;
    int c = t & 15;

    int j   = g_rowptr[i];
    int end = g_rowptr[i + 1];

    float4 a = make_float4(0.f, 0.f, 0.f, 0.f);
    float4 b = make_float4(0.f, 0.f, 0.f, 0.f);
    for (; j + 4 <= end; j += 4) {
        int s0 = g_adj[j], s1 = g_adj[j + 1], s2 = g_adj[j + 2], s3 = g_adj[j + 3];
        float n0 = g_norm[s0], n1 = g_norm[s1], n2 = g_norm[s2], n3 = g_norm[s3];
        float4 v0 = __ldg(feat4 + (s0 << 4) + c);
        float4 v1 = __ldg(feat4 + (s1 << 4) + c);
        float4 v2 = __ldg(feat4 + (s2 << 4) + c);
        float4 v3 = __ldg(feat4 + (s3 << 4) + c);
        a.x = fmaf(n0, v0.x, a.x); b.x = fmaf(n1, v1.x, b.x);
        a.y = fmaf(n0, v0.y, a.y); b.y = fmaf(n1, v1.y, b.y);
        a.z = fmaf(n0, v0.z, a.z); b.z = fmaf(n1, v1.z, b.z);
        a.w = fmaf(n0, v0.w, a.w); b.w = fmaf(n1, v1.w, b.w);
        a.x = fmaf(n2, v2.x, a.x); b.x = fmaf(n3, v3.x, b.x);
        a.y = fmaf(n2, v2.y, a.y); b.y = fmaf(n3, v3.y, b.y);
        a.z = fmaf(n2, v2.z, a.z); b.z = fmaf(n3, v3.z, b.z);
        a.w = fmaf(n2, v2.w, a.w); b.w = fmaf(n3, v3.w, b.w);
    }
    for (; j < end; j++) {
        int s = g_adj[j];
        float nv = g_norm[s];
        float4 v = __ldg(feat4 + (s << 4) + c);
        a.x = fmaf(nv, v.x, a.x);
        a.y = fmaf(nv, v.y, a.y);
        a.z = fmaf(nv, v.z, a.z);
        a.w = fmaf(nv, v.w, a.w);
    }
    a.x += b.x; a.y += b.y; a.z += b.z; a.w += b.w;
    g_h0[t] = a;
}

// ---------------------------------------------------------------------------
// 5) gather pass 1: xsB[s] = (C1A*norm[s]*h0[s] + C1B*feat[s]) * norm[s]
//                         = C1A*norm2[s]*h0[s]           (C1B == 0 at lam=2)
//    h1[i] = sum_{s in N(i)} xsB[s]; C1A applied once at the end.
// ---------------------------------------------------------------------------
__global__ __launch_bounds__(256) void gather1_kernel() {
    int t = blockIdx.x * blockDim.x + threadIdx.x;
    if (t >= NN * NROW4) return;
    int i = t >> 4;
    int c = t & 15;

    int j   = g_rowptr[i];
    int end = g_rowptr[i + 1];
    const float4* __restrict__ h0 = g_h0;

    float4 a = make_float4(0.f, 0.f, 0.f, 0.f);
    float4 b = make_float4(0.f, 0.f, 0.f, 0.f);
    for (; j + 4 <= end; j += 4) {
        int s0 = g_adj[j], s1 = g_adj[j + 1], s2 = g_adj[j + 2], s3 = g_adj[j + 3];
        float n0 = g_norm2[s0], n1 = g_norm2[s1], n2 = g_norm2[s2], n3 = g_norm2[s3];
        float4 v0 = h0[(s0 << 4) + c];
        float4 v1 = h0[(s1 << 4) + c];
        float4 v2 = h0[(s2 << 4) + c];
        float4 v3 = h0[(s3 << 4) + c];
        a.x = fmaf(n0, v0.x, a.x); b.x = fmaf(n1, v1.x, b.x);
        a.y = fmaf(n0, v0.y, a.y); b.y = fmaf(n1, v1.y, b.y);
        a.z = fmaf(n0, v0.z, a.z); b.z = fmaf(n1, v1.z, b.z);
        a.w = fmaf(n0, v0.w, a.w); b.w = fmaf(n1, v1.w, b.w);
        a.x = fmaf(n2, v2.x, a.x); b.x = fmaf(n3, v3.x, b.x);
        a.y = fmaf(n2, v2.y, a.y); b.y = fmaf(n3, v3.y, b.y);
        a.z = fmaf(n2, v2.z, a.z); b.z = fmaf(n3, v3.z, b.z);
        a.w = fmaf(n2, v2.w, a.w); b.w = fmaf(n3, v3.w, b.w);
    }
    for (; j < end; j++) {
        int s = g_adj[j];
        float nv = g_norm2[s];
        float4 v = h0[(s << 4) + c];
        a.x = fmaf(nv, v.x, a.x);
        a.y = fmaf(nv, v.y, a.y);
        a.z = fmaf(nv, v.z, a.z);
        a.w = fmaf(nv, v.w, a.w);
    }
    float4 r;
    r.x = C1A * (a.x + b.x);
    r.y = C1A * (a.y + b.y);
    r.z = C1A * (a.z + b.z);
    r.w = C1A * (a.w + b.w);
    g_h1[t] = r;
}

// ---------------------------------------------------------------------------
// 6) fused epilogue GEMM:
//    t0 = feat;  t1 = c1a*n*h0 + c1b*t0;  t2 = c2a*n*h1 + c2b*t1 - t0
//    out = t0@W0 + t1@W1 + t2@W2 + bias
//    256 threads = 4 col-groups (16 cols, warp-uniform) x 64 row-groups
//    (4 rows each). W (48KB) in shared; packed f32x2 accumulators.
// ---------------------------------------------------------------------------
__global__ __launch_bounds__(256) void final_kernel(
    const float4* __restrict__ feat4,
    const float4* __restrict__ W4,
    const float4* __restrict__ bias4,
    float4* __restrict__ out4) {
    __shared__ __align__(16) float Ws[3 * 64 * 64];   // 49152 B
    {
        float4* Ws4 = reinterpret_cast<float4*>(Ws);
        for (int i = threadIdx.x; i < 3 * 64 * 16; i += 256)
            Ws4[i] = __ldg(W4 + i);
    }
    __syncthreads();

    const int cg   = threadIdx.x >> 6;
    const int rg   = threadIdx.x & 63;
    const int base = blockIdx.x * 256;

    int   rows[4];
    bool  valid[4];
    float n[4];
#pragma unroll
    for (int r = 0; r < 4; r++) {
        int row  = base + rg + 64 * r;
        valid[r] = row < NN;
        rows[r]  = valid[r] ? row : 0;
        n[r]     = g_norm[rows[r]];
    }

    ull acc[4][8];
#pragma unroll
    for (int r = 0; r < 4; r++)
#pragma unroll
        for (int cp = 0; cp < 8; cp++) acc[r][cp] = 0ULL;

    const ulonglong2* Wp = reinterpret_cast<const ulonglong2*>(Ws);

    for (int dc = 0; dc < 16; dc++) {
        float4 a0[4], a1[4], a2[4];
#pragma unroll
        for (int r = 0; r < 4; r++) {
            int b = (rows[r] << 4) + dc;
            a0[r] = __ldg(feat4 + b);
            a1[r] = g_h0[b];
            a2[r] = g_h1[b];
        }
#pragma unroll
        for (int s = 0; s < 4; s++) {
            const int d = dc * 4 + s;
            ull tt[3][4];
#pragma unroll
            for (int r = 0; r < 4; r++) {
                float t0  = reinterpret_cast<const float*>(&a0[r])[s];
                float h0v = reinterpret_cast<const float*>(&a1[r])[s];
                float h1v = reinterpret_cast<const float*>(&a2[r])[s];
                float t1 = fmaf(C1A * n[r], h0v, C1B * t0);
                float t2 = fmaf(C2A * n[r], h1v, fmaf(C2B, t1, -t0));
                tt[0][r] = pack2(t0);
                tt[1][r] = pack2(t1);
                tt[2][r] = pack2(t2);
            }
#pragma unroll
            for (int k = 0; k < 3; k++) {
                const ulonglong2* p = Wp + (k * 1024 + d * 16 + cg * 4);
                ull w[8];
#pragma unroll
                for (int j = 0; j < 4; j++) {
                    ulonglong2 v = p[j];       // LDS.128, warp-uniform broadcast
                    w[2 * j]     = v.x;
                    w[2 * j + 1] = v.y;
                }
#pragma unroll
                for (int r = 0; r < 4; r++)
#pragma unroll
                    for (int cp = 0; cp < 8; cp++)
                        fma2(acc[r][cp], tt[k][r], w[cp]);
            }
        }
    }

    float4 b4[4];
#pragma unroll
    for (int j = 0; j < 4; j++) b4[j] = __ldg(bias4 + cg * 4 + j);
#pragma unroll
    for (int r = 0; r < 4; r++) {
        if (!valid[r]) continue;
#pragma unroll
        for (int j = 0; j < 4; j++) {
            float2 lo = unpack2(acc[r][2 * j]);
            float2 hi = unpack2(acc[r][2 * j + 1]);
            float4 o;
            o.x = lo.x + b4[j].x;
            o.y = lo.y + b4[j].y;
            o.z = hi.x + b4[j].z;
            o.w = hi.y + b4[j].w;
            out4[(rows[r] << 4) + cg * 4 + j] = o;
        }
    }
}

// ---------------------------------------------------------------------------
// launch (graph-capturable: only async memset + kernel launches)
// ---------------------------------------------------------------------------
extern "C" void kernel_launch(void* const* d_in, const int* in_sizes, int n_in,
                              void* d_out, int out_size) {
    const float* feat = (const float*)d_in[0];
    const float* W    = (const float*)d_in[1];
    const float* bias = (const float*)d_in[2];
    const int*   esrc = (const int*)d_in[3];
    const int*   edst = (const int*)d_in[4];
    float*       out  = (float*)d_out;

    void* p_degi = nullptr;
    cudaGetSymbolAddress(&p_degi, g_degi);
    cudaMemsetAsync(p_degi, 0, NN * sizeof(int));

    const int T = 256;

    deg_kernel<<<(NE / 4 + T - 1) / T, T>>>((const int4*)edst);
    norm_kernel<<<(NN + T - 1) / T, T>>>();
    blocksum_kernel<<<NB, 1024>>>();
    scanbsum_kernel<<<1, 128>>>();
    scanblock_kernel<<<NB, 1024>>>();
    fill_kernel<<<(NE / 4 + T - 1) / T, T>>>((const int4*)esrc, (const int4*)edst);

    gather0_kernel<<<(NN * NROW4 + T - 1) / T, T>>>((const float4*)feat);
    gather1_kernel<<<(NN * NROW4 + T - 1) / T, T>>>();

    final_kernel<<<(NN + 255) / 256, 256>>>((const float4*)feat,
                                            (const float4*)W,
                                            (const float4*)bias,
                                            (float4*)out);
}